// round 14
// baseline (speedup 1.0000x reference)
#include <cuda_runtime.h>
#include <cuda_fp16.h>
#include <math.h>

#define B_TOT 512
#define N_TOK 343
#define DIM   96
#define HEADS 3
#define HD    32
#define NW    64
#define CB_STRIDE 344
#define CB_SLICE  (N_TOK * CB_STRIDE)   // 117992
#define TABLE_LEN 2197
#define ONES_F16X2 0x3C003C00u
#define NEGINF2    0xFC00FC00u

// ---------------- scratch (device globals: no allocation allowed) ----------
__device__ __half g_ao[(size_t)B_TOT * N_TOK * DIM];         // [B][N][H*hd] fp16
__device__ __half g_cb[(size_t)NW * HEADS * CB_SLICE + 64];  // (mask+bias)*log2e, fp16

// ---------------- helpers --------------------------------------------------
__device__ __forceinline__ unsigned ex2_f16x2(unsigned x) {
    unsigned r;
    asm("ex2.approx.f16x2 %0, %1;" : "=r"(r) : "r"(x));
    return r;
}

__device__ __forceinline__ unsigned hadd2u(unsigned a, unsigned b) {
    unsigned r;
    asm("add.f16x2 %0, %1, %2;" : "=r"(r) : "r"(a), "r"(b));
    return r;
}

__device__ __forceinline__ unsigned f2tf(float x) {
    unsigned r;
    asm("cvt.rna.tf32.f32 %0, %1;" : "=r"(r) : "f"(x));
    return r;
}

// pack two f32 into f16x2: lo -> lower half, hi -> upper half
__device__ __forceinline__ unsigned pack_f16(float lo, float hi) {
    unsigned d;
    asm("cvt.rn.f16x2.f32 %0, %1, %2;" : "=r"(d) : "f"(hi), "f"(lo));
    return d;
}

__device__ __forceinline__ void mma_tf32(float& c0, float& c1, float& c2, float& c3,
                                         unsigned a0, unsigned a1, unsigned a2, unsigned a3,
                                         unsigned b0, unsigned b1) {
    asm volatile("mma.sync.aligned.m16n8k8.row.col.f32.tf32.tf32.f32 "
                 "{%0,%1,%2,%3}, {%4,%5,%6,%7}, {%8,%9}, {%0,%1,%2,%3};"
                 : "+f"(c0), "+f"(c1), "+f"(c2), "+f"(c3)
                 : "r"(a0), "r"(a1), "r"(a2), "r"(a3), "r"(b0), "r"(b1));
}

__device__ __forceinline__ void mma_f16(float& c0, float& c1, float& c2, float& c3,
                                        unsigned a0, unsigned a1, unsigned a2, unsigned a3,
                                        unsigned b0, unsigned b1) {
    asm volatile("mma.sync.aligned.m16n8k16.row.col.f32.f16.f16.f32 "
                 "{%0,%1,%2,%3}, {%4,%5,%6,%7}, {%8,%9}, {%0,%1,%2,%3};"
                 : "+f"(c0), "+f"(c1), "+f"(c2), "+f"(c3)
                 : "r"(a0), "r"(a1), "r"(a2), "r"(a3), "r"(b0), "r"(b1));
}

// vfrag HALF index for V value at (row j, col d)  (fp16 m16n8k16 B layout)
__device__ __forceinline__ int vhpos(int j, int d) {
    return (((j >> 4) * 4 + (d >> 3)) << 7)
         + (((d & 7) * 4 + ((j >> 1) & 3)) << 2) + (((j >> 3) & 1) << 1) + (j & 1);
}

// ---------------- kernel 0: fp16 combined bias table -----------------------
__global__ __launch_bounds__(352)
void cb_kernel(const float* __restrict__ mask,
               const float* __restrict__ rpb,
               const int*   __restrict__ relidx) {
    __shared__ float rpbs[TABLE_LEN];
    const int wh    = blockIdx.x;
    const int chunk = blockIdx.y;
    const int w     = wh / HEADS;
    const int h     = wh - w * HEADS;
    const int tid   = threadIdx.x;
    for (int t = tid; t < TABLE_LEN; t += 352)
        rpbs[t] = rpb[t * HEADS + h] * 1.4426950408889634f;
    __syncthreads();
    const int i0 = chunk * 86;
    const int i1 = (i0 + 86 < N_TOK) ? i0 + 86 : N_TOK;
    for (int i = i0; i < i1; i++) {
        if (tid < N_TOK) {
            int rel = relidx[i * N_TOK + tid];
            g_cb[(size_t)wh * CB_SLICE + i * CB_STRIDE + tid] =
                __float2half_rn(fmaf(mask[(size_t)w * N_TOK * N_TOK + i * N_TOK + tid],
                                     1.4426950408889634f, rpbs[rel]));
        } else if (tid == N_TOK) {
            g_cb[(size_t)wh * CB_SLICE + i * CB_STRIDE + N_TOK] = __float2half_rn(-1e30f); // -inf
        }
    }
}

// ---------------- kernel 1: FUSED qkv + attention --------------------------
// One CTA = (window, head). K/V as fp16 m16n8k16 B-fragments, Q as fp16
// A-fragments. Mainloop FULLY UNROLLED: per tile-pair, 4 fp16 QK mma ->
// pack -> HADD2 with fp16 cb -> ex2.f16x2 (== A-frag) -> 4 AV mma + ones mma.
// ptxas hoists the cb LDG.32s deep (high MLP) across the unrolled body.
__global__ __launch_bounds__(704, 1)
void attn_kernel(const float* __restrict__ xg,
                 const float* __restrict__ qkvw,
                 const float* __restrict__ qkvb) {
    extern __shared__ unsigned smu[];
    unsigned* kfrag = smu;               // [44*2][64] f16x2       :  5632 words
    unsigned* vfrag = smu + 5632;        // [22*4][64] f16x2       :  5632 words
    unsigned* wf    = smu + 11264;       // [3][4][12][64] tf32    :  9216 words
    unsigned* xs    = smu + 20480;       // [128][100] tf32 bits   : 12800 words
    float*    bsm   = (float*)(smu + 33280);   // [288]
    __half*   vh    = (__half*)vfrag;

    const int bid  = blockIdx.x;
    const int wh   = bid >> 3;                 // window*3 + h
    const int rep  = bid & 7;
    const int win  = wh / HEADS;
    const int h    = wh - win * HEADS;
    const int b    = rep * NW + win;
    const int tid  = threadIdx.x;
    const int lane = tid & 31;
    const int w    = tid >> 5;           // 0..21
    const int g    = lane >> 2;          // 0..7
    const int tig  = lane & 3;           // 0..3

    const float* xrow0 = xg + (size_t)b * N_TOK * DIM;
    const __half* cbp  = g_cb + (size_t)wh * CB_SLICE;
    const float qscale = 0.17677669529663687f * 1.4426950408889634f;  // /sqrt(32) * log2e

    // ---- stage weight B-fragments for this head ----
    for (int idx = tid; idx < 3 * 4 * 12 * 32; idx += 704) {
        int t = idx >> 5, l = idx & 31;
        int third = t / 48, rem = t - third * 48;
        int nt = rem / 12, kk = rem - nt * 12;
        int gl = l >> 2, tl = l & 3;
        int c  = third * 96 + h * 32 + nt * 8 + gl;
        int k0 = kk * 8 + tl;
        wf[t * 64 + l * 2]     = f2tf(qkvw[c * 96 + k0]);
        wf[t * 64 + l * 2 + 1] = f2tf(qkvw[c * 96 + k0 + 4]);
    }
    for (int idx = tid; idx < 96; idx += 704) {
        bsm[idx] = qkvb[idx + h * 32 + ((idx >> 5) * 64)];  // bsm[third*32+cc] = qkvb[third*96+h*32+cc]
    }

    unsigned qa[2][4];   // fp16 Q A-fragments, 2 k16 chunks

    // ---- chunks of 128 rows: compute K,V into frags; Q for owning warps ----
    #pragma unroll 1
    for (int c = 0; c < 3; c++) {
        if (c > 0) __syncthreads();
        for (int idx = tid; idx < 128 * 96; idx += 704) {
            int r = idx / 96, cc = idx - r * 96;
            int n = 128 * c + r;
            float v = (n < N_TOK) ? xrow0[(size_t)n * 96 + cc] : 0.f;
            xs[r * 100 + cc] = f2tf(v);
        }
        __syncthreads();

        // K/V units: u = (s<<2) | (third01<<1) | nhalf, 32 units over 22 warps
        for (int u = w; u < 32; u += 22) {
            int s = u >> 2, th = (u >> 1) & 1, nh = u & 1;
            const unsigned* xrA = xs + (s * 16 + g) * 100;
            const unsigned* xrB = xrA + 800;
            #pragma unroll
            for (int ntl = 0; ntl < 2; ntl++) {
                int nt = nh * 2 + ntl;
                float a0f = 0.f, a1f = 0.f, a2f = 0.f, a3f = 0.f;
                #pragma unroll
                for (int kk = 0; kk < 12; kk++) {
                    unsigned a0 = xrA[kk * 8 + tig];
                    unsigned a1 = xrB[kk * 8 + tig];
                    unsigned a2 = xrA[kk * 8 + tig + 4];
                    unsigned a3 = xrB[kk * 8 + tig + 4];
                    uint2 bb = *(const uint2*)(wf + (((th + 1) * 48) + nt * 12 + kk) * 64 + lane * 2);
                    mma_tf32(a0f, a1f, a2f, a3f, a0, a1, a2, a3, bb.x, bb.y);
                }
                int c0 = nt * 8 + 2 * tig;
                float b0 = bsm[(th + 1) * 32 + c0];
                float b1 = bsm[(th + 1) * 32 + c0 + 1];
                int nA = 128 * c + s * 16 + g;
                int nB = nA + 8;
                float v00 = a0f + b0, v01 = a1f + b1;    // row nA
                float v10 = a2f + b0, v11 = a3f + b1;    // row nB
                if (th == 0) {
                    int tcol = nt >> 1, reg = nt & 1;
                    if (nA < 352)
                        kfrag[((((nA >> 3) << 1) + tcol) << 6) + (lane << 1) + reg] = pack_f16(v00, v01);
                    if (nB < 352)
                        kfrag[((((nB >> 3) << 1) + tcol) << 6) + (lane << 1) + reg] = pack_f16(v10, v11);
                } else {
                    if (nA < 352) {
                        vh[vhpos(nA, c0)]     = __float2half_rn(v00);
                        vh[vhpos(nA, c0 + 1)] = __float2half_rn(v01);
                    }
                    if (nB < 352) {
                        vh[vhpos(nB, c0)]     = __float2half_rn(v10);
                        vh[vhpos(nB, c0 + 1)] = __float2half_rn(v11);
                    }
                }
            }
        }

        // Q for warps whose stripe lives in this chunk: direct fp16 pack
        if ((w >> 3) == c) {
            const int s = w & 7;
            const unsigned* xrA = xs + (s * 16 + g) * 100;
            const unsigned* xrB = xrA + 800;
            #pragma unroll
            for (int nt = 0; nt < 4; nt++) {
                float a0f = 0.f, a1f = 0.f, a2f = 0.f, a3f = 0.f;
                #pragma unroll
                for (int kk = 0; kk < 12; kk++) {
                    unsigned a0 = xrA[kk * 8 + tig];
                    unsigned a1 = xrB[kk * 8 + tig];
                    unsigned a2 = xrA[kk * 8 + tig + 4];
                    unsigned a3 = xrB[kk * 8 + tig + 4];
                    uint2 bb = *(const uint2*)(wf + (nt * 12 + kk) * 64 + lane * 2);
                    mma_tf32(a0f, a1f, a2f, a3f, a0, a1, a2, a3, bb.x, bb.y);
                }
                int c0 = nt * 8 + 2 * tig;
                float b0 = bsm[c0], b1 = bsm[c0 + 1];
                qa[nt >> 1][(nt & 1) * 2 + 0] = pack_f16((a0f + b0) * qscale, (a1f + b1) * qscale);
                qa[nt >> 1][(nt & 1) * 2 + 1] = pack_f16((a2f + b0) * qscale, (a3f + b1) * qscale);
            }
        }
    }
    __syncthreads();

    // ---- mainloop (fully unrolled; ptxas hoists cb LDGs for deep MLP) ----
    const int i0 = w * 16;
    const int iA = i0 + g, iB = i0 + g + 8;
    const bool vA = (iA < N_TOK), vB = (iB < N_TOK);

    float av[5][4];   // [0..3]: output n8 tiles; [4]: ones-column rowsums
    #pragma unroll
    for (int nn = 0; nn < 5; nn++)
        #pragma unroll
        for (int e = 0; e < 4; e++) av[nn][e] = 0.f;

    const __half* cbAh = cbp + (size_t)iA * CB_STRIDE;
    const __half* cbBh = cbp + (size_t)iB * CB_STRIDE;

    #pragma unroll
    for (int tp = 0; tp < 22; tp++) {
        unsigned af[4];
        #pragma unroll
        for (int tt = 0; tt < 2; tt++) {
            const int ntg = 2 * tp + tt;
            const int j0  = ntg * 8 + 2 * tig;

            unsigned pa, pb;
            if (ntg < 43) {            // compile-time branch
                pa = vA ? *(const unsigned*)(cbAh + j0) : NEGINF2;
                pb = vB ? *(const unsigned*)(cbBh + j0) : NEGINF2;
            } else {
                pa = NEGINF2; pb = NEGINF2;
            }

            float c0 = 0.f, c1 = 0.f, c2 = 0.f, c3 = 0.f;
            uint2 bk0 = *(const uint2*)(kfrag + (ntg * 2 + 0) * 64 + lane * 2);
            uint2 bk1 = *(const uint2*)(kfrag + (ntg * 2 + 1) * 64 + lane * 2);
            mma_f16(c0, c1, c2, c3, qa[0][0], qa[0][1], qa[0][2], qa[0][3], bk0.x, bk0.y);
            mma_f16(c0, c1, c2, c3, qa[1][0], qa[1][1], qa[1][2], qa[1][3], bk1.x, bk1.y);

            unsigned s0 = hadd2u(pack_f16(c0, c1), pa);
            unsigned s1 = hadd2u(pack_f16(c2, c3), pb);
            af[tt * 2 + 0] = ex2_f16x2(s0);   // row g
            af[tt * 2 + 1] = ex2_f16x2(s1);   // row g+8
        }

        #pragma unroll
        for (int nn = 0; nn < 4; nn++) {
            uint2 bb = *(const uint2*)(vfrag + (tp * 4 + nn) * 64 + lane * 2);
            mma_f16(av[nn][0], av[nn][1], av[nn][2], av[nn][3],
                    af[0], af[1], af[2], af[3], bb.x, bb.y);
        }
        mma_f16(av[4][0], av[4][1], av[4][2], av[4][3],
                af[0], af[1], af[2], af[3], ONES_F16X2, ONES_F16X2);
    }

    const float invA = 1.0f / av[4][0];
    const float invB = 1.0f / av[4][2];

    __half* aoh = g_ao;
    #pragma unroll
    for (int nn = 0; nn < 4; nn++) {
        const int d = nn * 8 + 2 * tig;
        if (vA) {
            unsigned o = pack_f16(av[nn][0] * invA, av[nn][1] * invA);
            *(unsigned*)(aoh + ((size_t)b * N_TOK + iA) * DIM + h * HD + d) = o;
        }
        if (vB) {
            unsigned o = pack_f16(av[nn][2] * invB, av[nn][3] * invB);
            *(unsigned*)(aoh + ((size_t)b * N_TOK + iB) * DIM + h * HD + d) = o;
        }
    }
}

// ---------------- kernel 2: output projection (reads fp16 g_ao) ------------
__global__ __launch_bounds__(256, 2)
void proj_kernel(const float* __restrict__ w,
                 const float* __restrict__ bias,
                 float* __restrict__ out) {
    extern __shared__ float smf[];
    unsigned* xs    = (unsigned*)smf;            // [128][100] tf32 bits
    unsigned* wfrag = (unsigned*)smf + 12800;    // [144][64]
    float*    bs    = smf + 12800 + 9216;        // [96]
    const int tid = threadIdx.x;
    const int m0  = blockIdx.x * 128;

    for (int idx = tid; idx < 12 * 12 * 32; idx += 256) {
        int t = idx >> 5, l = idx & 31;
        int nt = t / 12, kk = t - nt * 12;
        int gl = l >> 2, tl = l & 3;
        int c  = nt * 8 + gl;
        int k0 = kk * 8 + tl;
        wfrag[t * 64 + l * 2]     = f2tf(w[c * 96 + k0]);
        wfrag[t * 64 + l * 2 + 1] = f2tf(w[c * 96 + k0 + 4]);
    }
    if (tid < 96) bs[tid] = bias[tid];
    {
        const __half2* src = (const __half2*)(g_ao + (size_t)m0 * 96);
        for (int idx = tid; idx < 128 * 48; idx += 256) {
            int r = idx / 48, c2 = idx - r * 48;
            float2 v = __half22float2(src[idx]);
            xs[r * 100 + c2 * 2]     = f2tf(v.x);
            xs[r * 100 + c2 * 2 + 1] = f2tf(v.y);
        }
    }
    __syncthreads();

    const int wp   = tid >> 5;
    const int lane = tid & 31;
    const int g    = lane >> 2;
    const int tig  = lane & 3;
    const int cg   = wp & 3;
    const int mh   = wp >> 2;

    uint2 breg[12][3];
    #pragma unroll
    for (int kk = 0; kk < 12; kk++)
        #pragma unroll
        for (int ntl = 0; ntl < 3; ntl++)
            breg[kk][ntl] = *(const uint2*)(wfrag + ((3 * cg + ntl) * 12 + kk) * 64 + lane * 2);

    #pragma unroll
    for (int s = 0; s < 4; s++) {
        const unsigned* xrA = xs + (mh * 64 + s * 16 + g) * 100;
        const unsigned* xrB = xrA + 800;

        float acc[3][4];
        #pragma unroll
        for (int ntl = 0; ntl < 3; ntl++)
            #pragma unroll
            for (int e = 0; e < 4; e++) acc[ntl][e] = 0.f;

        #pragma unroll
        for (int kk = 0; kk < 12; kk++) {
            unsigned a0 = xrA[kk * 8 + tig];
            unsigned a1 = xrB[kk * 8 + tig];
            unsigned a2 = xrA[kk * 8 + tig + 4];
            unsigned a3 = xrB[kk * 8 + tig + 4];
            #pragma unroll
            for (int ntl = 0; ntl < 3; ntl++)
                mma_tf32(acc[ntl][0], acc[ntl][1], acc[ntl][2], acc[ntl][3],
                         a0, a1, a2, a3, breg[kk][ntl].x, breg[kk][ntl].y);
        }

        const size_t mA = m0 + mh * 64 + s * 16 + g;
        const size_t mB = mA + 8;
        #pragma unroll
        for (int ntl = 0; ntl < 3; ntl++) {
            int c0 = (3 * cg + ntl) * 8 + 2 * tig;
            float bb0 = bs[c0], bb1 = bs[c0 + 1];
            *(float2*)(out + mA * 96 + c0) = make_float2(acc[ntl][0] + bb0, acc[ntl][1] + bb1);
            *(float2*)(out + mB * 96 + c0) = make_float2(acc[ntl][2] + bb0, acc[ntl][3] + bb1);
        }
    }
}

// ---------------- launch ---------------------------------------------------
extern "C" void kernel_launch(void* const* d_in, const int* in_sizes, int n_in,
                              void* d_out, int out_size) {
    const float* x      = (const float*)d_in[0];
    const float* mask   = (const float*)d_in[1];
    const float* qkv_w  = (const float*)d_in[2];
    const float* qkv_b  = (const float*)d_in[3];
    const float* proj_w = (const float*)d_in[4];
    const float* proj_b = (const float*)d_in[5];
    const float* rpb    = (const float*)d_in[6];
    const int*   relidx = (const int*)d_in[7];
    float* out = (float*)d_out;

    const int smem_attn = (5632 + 5632 + 9216 + 12800 + 288) * 4;  // 134,272 B
    const int smem_proj = (12800 + 9216 + 96) * 4;                 //  88,448 B
    cudaFuncSetAttribute(attn_kernel, cudaFuncAttributeMaxDynamicSharedMemorySize, smem_attn);
    cudaFuncSetAttribute(proj_kernel, cudaFuncAttributeMaxDynamicSharedMemorySize, smem_proj);

    cb_kernel  <<<dim3(NW * HEADS, 4), 352>>>(mask, rpb, relidx);
    attn_kernel<<<B_TOT * HEADS, 704, smem_attn>>>(x, qkv_w, qkv_b);
    proj_kernel<<<1372, 256, smem_proj>>>(proj_w, proj_b, out);
    (void)in_sizes; (void)n_in; (void)out_size;
}

// round 15
// speedup vs baseline: 1.0491x; 1.0491x over previous
#include <cuda_runtime.h>
#include <cuda_fp16.h>
#include <math.h>

#define B_TOT 512
#define N_TOK 343
#define DIM   96
#define HEADS 3
#define HD    32
#define NW    64
#define CB_STRIDE 344
#define CB_SLICE  (N_TOK * CB_STRIDE)   // 117992
#define TABLE_LEN 2197
#define ONES_F16X2 0x3C003C00u
#define NEGINF2    0xFC00FC00u

// ---------------- scratch (device globals: no allocation allowed) ----------
__device__ __half g_ao[(size_t)B_TOT * N_TOK * DIM];         // [B][N][H*hd] fp16
__device__ __half g_cb[(size_t)NW * HEADS * CB_SLICE + 64];  // (mask+bias)*log2e, fp16

// ---------------- helpers --------------------------------------------------
__device__ __forceinline__ unsigned ex2_f16x2(unsigned x) {
    unsigned r;
    asm("ex2.approx.f16x2 %0, %1;" : "=r"(r) : "r"(x));
    return r;
}

__device__ __forceinline__ unsigned hadd2u(unsigned a, unsigned b) {
    unsigned r;
    asm("add.f16x2 %0, %1, %2;" : "=r"(r) : "r"(a), "r"(b));
    return r;
}

__device__ __forceinline__ unsigned f2tf(float x) {
    unsigned r;
    asm("cvt.rna.tf32.f32 %0, %1;" : "=r"(r) : "f"(x));
    return r;
}

// pack two f32 into f16x2: lo -> lower half, hi -> upper half
__device__ __forceinline__ unsigned pack_f16(float lo, float hi) {
    unsigned d;
    asm("cvt.rn.f16x2.f32 %0, %1, %2;" : "=r"(d) : "f"(hi), "f"(lo));
    return d;
}

__device__ __forceinline__ void mma_tf32(float& c0, float& c1, float& c2, float& c3,
                                         unsigned a0, unsigned a1, unsigned a2, unsigned a3,
                                         unsigned b0, unsigned b1) {
    asm volatile("mma.sync.aligned.m16n8k8.row.col.f32.tf32.tf32.f32 "
                 "{%0,%1,%2,%3}, {%4,%5,%6,%7}, {%8,%9}, {%0,%1,%2,%3};"
                 : "+f"(c0), "+f"(c1), "+f"(c2), "+f"(c3)
                 : "r"(a0), "r"(a1), "r"(a2), "r"(a3), "r"(b0), "r"(b1));
}

__device__ __forceinline__ void mma_f16(float& c0, float& c1, float& c2, float& c3,
                                        unsigned a0, unsigned a1, unsigned a2, unsigned a3,
                                        unsigned b0, unsigned b1) {
    asm volatile("mma.sync.aligned.m16n8k16.row.col.f32.f16.f16.f32 "
                 "{%0,%1,%2,%3}, {%4,%5,%6,%7}, {%8,%9}, {%0,%1,%2,%3};"
                 : "+f"(c0), "+f"(c1), "+f"(c2), "+f"(c3)
                 : "r"(a0), "r"(a1), "r"(a2), "r"(a3), "r"(b0), "r"(b1));
}

// vfrag HALF index for V value at (row j, col d)  (fp16 m16n8k16 B layout)
__device__ __forceinline__ int vhpos(int j, int d) {
    return (((j >> 4) * 4 + (d >> 3)) << 7)
         + (((d & 7) * 4 + ((j >> 1) & 3)) << 2) + (((j >> 3) & 1) << 1) + (j & 1);
}

// ---------------- kernel 0: fp16 cb table with PACKED 4-byte stores --------
// Each thread computes its fp16 value; even lanes merge the odd neighbor's
// bits via shfl and issue one STG.32 (16 lanes x 4B = 64B contiguous/warp).
__global__ __launch_bounds__(352)
void cb_kernel(const float* __restrict__ mask,
               const float* __restrict__ rpb,
               const int*   __restrict__ relidx) {
    __shared__ float rpbs[TABLE_LEN];
    const int wh    = blockIdx.x;
    const int chunk = blockIdx.y;
    const int w     = wh / HEADS;
    const int h     = wh - w * HEADS;
    const int tid   = threadIdx.x;
    for (int t = tid; t < TABLE_LEN; t += 352)
        rpbs[t] = rpb[t * HEADS + h] * 1.4426950408889634f;
    __syncthreads();

    unsigned* dst = (unsigned*)(g_cb + (size_t)wh * CB_SLICE);
    const int i0 = chunk * 86;
    const int i1 = (i0 + 86 < N_TOK) ? i0 + 86 : N_TOK;
    for (int i = i0; i < i1; i++) {
        unsigned hb = 0xFC00u;    // fp16 -inf (pad j=343 and inactive tails)
        if (tid < N_TOK) {
            int rel = relidx[i * N_TOK + tid];
            float v = fmaf(mask[(size_t)w * N_TOK * N_TOK + i * N_TOK + tid],
                           1.4426950408889634f, rpbs[rel]);
            hb = (unsigned)__half_as_ushort(__float2half_rn(v));
        }
        unsigned up = __shfl_down_sync(0xffffffffu, hb, 1);
        if (!(tid & 1) && tid < CB_STRIDE)
            dst[i * (CB_STRIDE / 2) + (tid >> 1)] = (hb & 0xFFFFu) | (up << 16);
    }
}

// ---------------- kernel 1: FUSED qkv + attention (unchanged from R14) -----
__global__ __launch_bounds__(704, 1)
void attn_kernel(const float* __restrict__ xg,
                 const float* __restrict__ qkvw,
                 const float* __restrict__ qkvb) {
    extern __shared__ unsigned smu[];
    unsigned* kfrag = smu;               // [44*2][64] f16x2       :  5632 words
    unsigned* vfrag = smu + 5632;        // [22*4][64] f16x2       :  5632 words
    unsigned* wf    = smu + 11264;       // [3][4][12][64] tf32    :  9216 words
    unsigned* xs    = smu + 20480;       // [128][100] tf32 bits   : 12800 words
    float*    bsm   = (float*)(smu + 33280);   // [288]
    __half*   vh    = (__half*)vfrag;

    const int bid  = blockIdx.x;
    const int wh   = bid >> 3;                 // window*3 + h
    const int rep  = bid & 7;
    const int win  = wh / HEADS;
    const int h    = wh - win * HEADS;
    const int b    = rep * NW + win;
    const int tid  = threadIdx.x;
    const int lane = tid & 31;
    const int w    = tid >> 5;           // 0..21
    const int g    = lane >> 2;          // 0..7
    const int tig  = lane & 3;           // 0..3

    const float* xrow0 = xg + (size_t)b * N_TOK * DIM;
    const __half* cbp  = g_cb + (size_t)wh * CB_SLICE;
    const float qscale = 0.17677669529663687f * 1.4426950408889634f;  // /sqrt(32) * log2e

    // ---- stage weight B-fragments for this head ----
    for (int idx = tid; idx < 3 * 4 * 12 * 32; idx += 704) {
        int t = idx >> 5, l = idx & 31;
        int third = t / 48, rem = t - third * 48;
        int nt = rem / 12, kk = rem - nt * 12;
        int gl = l >> 2, tl = l & 3;
        int c  = third * 96 + h * 32 + nt * 8 + gl;
        int k0 = kk * 8 + tl;
        wf[t * 64 + l * 2]     = f2tf(qkvw[c * 96 + k0]);
        wf[t * 64 + l * 2 + 1] = f2tf(qkvw[c * 96 + k0 + 4]);
    }
    for (int idx = tid; idx < 96; idx += 704) {
        bsm[idx] = qkvb[idx + h * 32 + ((idx >> 5) * 64)];  // bsm[third*32+cc] = qkvb[third*96+h*32+cc]
    }

    unsigned qa[2][4];   // fp16 Q A-fragments, 2 k16 chunks

    // ---- chunks of 128 rows: compute K,V into frags; Q for owning warps ----
    #pragma unroll 1
    for (int c = 0; c < 3; c++) {
        if (c > 0) __syncthreads();
        for (int idx = tid; idx < 128 * 96; idx += 704) {
            int r = idx / 96, cc = idx - r * 96;
            int n = 128 * c + r;
            float v = (n < N_TOK) ? xrow0[(size_t)n * 96 + cc] : 0.f;
            xs[r * 100 + cc] = f2tf(v);
        }
        __syncthreads();

        // K/V units: u = (s<<2) | (third01<<1) | nhalf, 32 units over 22 warps
        for (int u = w; u < 32; u += 22) {
            int s = u >> 2, th = (u >> 1) & 1, nh = u & 1;
            const unsigned* xrA = xs + (s * 16 + g) * 100;
            const unsigned* xrB = xrA + 800;
            #pragma unroll
            for (int ntl = 0; ntl < 2; ntl++) {
                int nt = nh * 2 + ntl;
                float a0f = 0.f, a1f = 0.f, a2f = 0.f, a3f = 0.f;
                #pragma unroll
                for (int kk = 0; kk < 12; kk++) {
                    unsigned a0 = xrA[kk * 8 + tig];
                    unsigned a1 = xrB[kk * 8 + tig];
                    unsigned a2 = xrA[kk * 8 + tig + 4];
                    unsigned a3 = xrB[kk * 8 + tig + 4];
                    uint2 bb = *(const uint2*)(wf + (((th + 1) * 48) + nt * 12 + kk) * 64 + lane * 2);
                    mma_tf32(a0f, a1f, a2f, a3f, a0, a1, a2, a3, bb.x, bb.y);
                }
                int c0 = nt * 8 + 2 * tig;
                float b0 = bsm[(th + 1) * 32 + c0];
                float b1 = bsm[(th + 1) * 32 + c0 + 1];
                int nA = 128 * c + s * 16 + g;
                int nB = nA + 8;
                float v00 = a0f + b0, v01 = a1f + b1;    // row nA
                float v10 = a2f + b0, v11 = a3f + b1;    // row nB
                if (th == 0) {
                    int tcol = nt >> 1, reg = nt & 1;
                    if (nA < 352)
                        kfrag[((((nA >> 3) << 1) + tcol) << 6) + (lane << 1) + reg] = pack_f16(v00, v01);
                    if (nB < 352)
                        kfrag[((((nB >> 3) << 1) + tcol) << 6) + (lane << 1) + reg] = pack_f16(v10, v11);
                } else {
                    if (nA < 352) {
                        vh[vhpos(nA, c0)]     = __float2half_rn(v00);
                        vh[vhpos(nA, c0 + 1)] = __float2half_rn(v01);
                    }
                    if (nB < 352) {
                        vh[vhpos(nB, c0)]     = __float2half_rn(v10);
                        vh[vhpos(nB, c0 + 1)] = __float2half_rn(v11);
                    }
                }
            }
        }

        // Q for warps whose stripe lives in this chunk: direct fp16 pack
        if ((w >> 3) == c) {
            const int s = w & 7;
            const unsigned* xrA = xs + (s * 16 + g) * 100;
            const unsigned* xrB = xrA + 800;
            #pragma unroll
            for (int nt = 0; nt < 4; nt++) {
                float a0f = 0.f, a1f = 0.f, a2f = 0.f, a3f = 0.f;
                #pragma unroll
                for (int kk = 0; kk < 12; kk++) {
                    unsigned a0 = xrA[kk * 8 + tig];
                    unsigned a1 = xrB[kk * 8 + tig];
                    unsigned a2 = xrA[kk * 8 + tig + 4];
                    unsigned a3 = xrB[kk * 8 + tig + 4];
                    uint2 bb = *(const uint2*)(wf + (nt * 12 + kk) * 64 + lane * 2);
                    mma_tf32(a0f, a1f, a2f, a3f, a0, a1, a2, a3, bb.x, bb.y);
                }
                int c0 = nt * 8 + 2 * tig;
                float b0 = bsm[c0], b1 = bsm[c0 + 1];
                qa[nt >> 1][(nt & 1) * 2 + 0] = pack_f16((a0f + b0) * qscale, (a1f + b1) * qscale);
                qa[nt >> 1][(nt & 1) * 2 + 1] = pack_f16((a2f + b0) * qscale, (a3f + b1) * qscale);
            }
        }
    }
    __syncthreads();

    // ---- mainloop (fully unrolled; ptxas hoists cb LDGs for deep MLP) ----
    const int i0 = w * 16;
    const int iA = i0 + g, iB = i0 + g + 8;
    const bool vA = (iA < N_TOK), vB = (iB < N_TOK);

    float av[5][4];   // [0..3]: output n8 tiles; [4]: ones-column rowsums
    #pragma unroll
    for (int nn = 0; nn < 5; nn++)
        #pragma unroll
        for (int e = 0; e < 4; e++) av[nn][e] = 0.f;

    const __half* cbAh = cbp + (size_t)iA * CB_STRIDE;
    const __half* cbBh = cbp + (size_t)iB * CB_STRIDE;

    #pragma unroll
    for (int tp = 0; tp < 22; tp++) {
        unsigned af[4];
        #pragma unroll
        for (int tt = 0; tt < 2; tt++) {
            const int ntg = 2 * tp + tt;
            const int j0  = ntg * 8 + 2 * tig;

            unsigned pa, pb;
            if (ntg < 43) {            // compile-time branch
                pa = vA ? *(const unsigned*)(cbAh + j0) : NEGINF2;
                pb = vB ? *(const unsigned*)(cbBh + j0) : NEGINF2;
            } else {
                pa = NEGINF2; pb = NEGINF2;
            }

            float c0 = 0.f, c1 = 0.f, c2 = 0.f, c3 = 0.f;
            uint2 bk0 = *(const uint2*)(kfrag + (ntg * 2 + 0) * 64 + lane * 2);
            uint2 bk1 = *(const uint2*)(kfrag + (ntg * 2 + 1) * 64 + lane * 2);
            mma_f16(c0, c1, c2, c3, qa[0][0], qa[0][1], qa[0][2], qa[0][3], bk0.x, bk0.y);
            mma_f16(c0, c1, c2, c3, qa[1][0], qa[1][1], qa[1][2], qa[1][3], bk1.x, bk1.y);

            unsigned s0 = hadd2u(pack_f16(c0, c1), pa);
            unsigned s1 = hadd2u(pack_f16(c2, c3), pb);
            af[tt * 2 + 0] = ex2_f16x2(s0);   // row g
            af[tt * 2 + 1] = ex2_f16x2(s1);   // row g+8
        }

        #pragma unroll
        for (int nn = 0; nn < 4; nn++) {
            uint2 bb = *(const uint2*)(vfrag + (tp * 4 + nn) * 64 + lane * 2);
            mma_f16(av[nn][0], av[nn][1], av[nn][2], av[nn][3],
                    af[0], af[1], af[2], af[3], bb.x, bb.y);
        }
        mma_f16(av[4][0], av[4][1], av[4][2], av[4][3],
                af[0], af[1], af[2], af[3], ONES_F16X2, ONES_F16X2);
    }

    const float invA = 1.0f / av[4][0];
    const float invB = 1.0f / av[4][2];

    __half* aoh = g_ao;
    #pragma unroll
    for (int nn = 0; nn < 4; nn++) {
        const int d = nn * 8 + 2 * tig;
        if (vA) {
            unsigned o = pack_f16(av[nn][0] * invA, av[nn][1] * invA);
            *(unsigned*)(aoh + ((size_t)b * N_TOK + iA) * DIM + h * HD + d) = o;
        }
        if (vB) {
            unsigned o = pack_f16(av[nn][2] * invB, av[nn][3] * invB);
            *(unsigned*)(aoh + ((size_t)b * N_TOK + iB) * DIM + h * HD + d) = o;
        }
    }
}

// ---------------- kernel 2: output projection (reads fp16 g_ao) ------------
__global__ __launch_bounds__(256, 2)
void proj_kernel(const float* __restrict__ w,
                 const float* __restrict__ bias,
                 float* __restrict__ out) {
    extern __shared__ float smf[];
    unsigned* xs    = (unsigned*)smf;            // [128][100] tf32 bits
    unsigned* wfrag = (unsigned*)smf + 12800;    // [144][64]
    float*    bs    = smf + 12800 + 9216;        // [96]
    const int tid = threadIdx.x;
    const int m0  = blockIdx.x * 128;

    for (int idx = tid; idx < 12 * 12 * 32; idx += 256) {
        int t = idx >> 5, l = idx & 31;
        int nt = t / 12, kk = t - nt * 12;
        int gl = l >> 2, tl = l & 3;
        int c  = nt * 8 + gl;
        int k0 = kk * 8 + tl;
        wfrag[t * 64 + l * 2]     = f2tf(w[c * 96 + k0]);
        wfrag[t * 64 + l * 2 + 1] = f2tf(w[c * 96 + k0 + 4]);
    }
    if (tid < 96) bs[tid] = bias[tid];
    {
        const __half2* src = (const __half2*)(g_ao + (size_t)m0 * 96);
        for (int idx = tid; idx < 128 * 48; idx += 256) {
            int r = idx / 48, c2 = idx - r * 48;
            float2 v = __half22float2(src[idx]);
            xs[r * 100 + c2 * 2]     = f2tf(v.x);
            xs[r * 100 + c2 * 2 + 1] = f2tf(v.y);
        }
    }
    __syncthreads();

    const int wp   = tid >> 5;
    const int lane = tid & 31;
    const int g    = lane >> 2;
    const int tig  = lane & 3;
    const int cg   = wp & 3;
    const int mh   = wp >> 2;

    uint2 breg[12][3];
    #pragma unroll
    for (int kk = 0; kk < 12; kk++)
        #pragma unroll
        for (int ntl = 0; ntl < 3; ntl++)
            breg[kk][ntl] = *(const uint2*)(wfrag + ((3 * cg + ntl) * 12 + kk) * 64 + lane * 2);

    #pragma unroll
    for (int s = 0; s < 4; s++) {
        const unsigned* xrA = xs + (mh * 64 + s * 16 + g) * 100;
        const unsigned* xrB = xrA + 800;

        float acc[3][4];
        #pragma unroll
        for (int ntl = 0; ntl < 3; ntl++)
            #pragma unroll
            for (int e = 0; e < 4; e++) acc[ntl][e] = 0.f;

        #pragma unroll
        for (int kk = 0; kk < 12; kk++) {
            unsigned a0 = xrA[kk * 8 + tig];
            unsigned a1 = xrB[kk * 8 + tig];
            unsigned a2 = xrA[kk * 8 + tig + 4];
            unsigned a3 = xrB[kk * 8 + tig + 4];
            #pragma unroll
            for (int ntl = 0; ntl < 3; ntl++)
                mma_tf32(acc[ntl][0], acc[ntl][1], acc[ntl][2], acc[ntl][3],
                         a0, a1, a2, a3, breg[kk][ntl].x, breg[kk][ntl].y);
        }

        const size_t mA = m0 + mh * 64 + s * 16 + g;
        const size_t mB = mA + 8;
        #pragma unroll
        for (int ntl = 0; ntl < 3; ntl++) {
            int c0 = (3 * cg + ntl) * 8 + 2 * tig;
            float bb0 = bs[c0], bb1 = bs[c0 + 1];
            *(float2*)(out + mA * 96 + c0) = make_float2(acc[ntl][0] + bb0, acc[ntl][1] + bb1);
            *(float2*)(out + mB * 96 + c0) = make_float2(acc[ntl][2] + bb0, acc[ntl][3] + bb1);
        }
    }
}

// ---------------- launch ---------------------------------------------------
extern "C" void kernel_launch(void* const* d_in, const int* in_sizes, int n_in,
                              void* d_out, int out_size) {
    const float* x      = (const float*)d_in[0];
    const float* mask   = (const float*)d_in[1];
    const float* qkv_w  = (const float*)d_in[2];
    const float* qkv_b  = (const float*)d_in[3];
    const float* proj_w = (const float*)d_in[4];
    const float* proj_b = (const float*)d_in[5];
    const float* rpb    = (const float*)d_in[6];
    const int*   relidx = (const int*)d_in[7];
    float* out = (float*)d_out;

    const int smem_attn = (5632 + 5632 + 9216 + 12800 + 288) * 4;  // 134,272 B
    const int smem_proj = (12800 + 9216 + 96) * 4;                 //  88,448 B
    cudaFuncSetAttribute(attn_kernel, cudaFuncAttributeMaxDynamicSharedMemorySize, smem_attn);
    cudaFuncSetAttribute(proj_kernel, cudaFuncAttributeMaxDynamicSharedMemorySize, smem_proj);

    cb_kernel  <<<dim3(NW * HEADS, 4), 352>>>(mask, rpb, relidx);
    attn_kernel<<<B_TOT * HEADS, 704, smem_attn>>>(x, qkv_w, qkv_b);
    proj_kernel<<<1372, 256, smem_proj>>>(proj_w, proj_b, out);
    (void)in_sizes; (void)n_in; (void)out_size;
}

// round 16
// speedup vs baseline: 1.1944x; 1.1385x over previous
#include <cuda_runtime.h>
#include <cuda_fp16.h>
#include <math.h>

#define B_TOT 512
#define N_TOK 343
#define DIM   96
#define HEADS 3
#define HD    32
#define NW    64
#define CB_STRIDE 344
#define CB_SLICE  (N_TOK * CB_STRIDE)   // 117992
#define ONES_F16X2 0x3C003C00u
#define NEGINF2    0xFC00FC00u

// ---------------- scratch (device globals: no allocation allowed) ----------
__device__ __half g_ao[(size_t)B_TOT * N_TOK * DIM];         // [B][N][H*hd] fp16
__device__ __half g_cb[(size_t)NW * HEADS * CB_SLICE + 64];  // (mask+bias)*log2e, fp16
__device__ float  g_rpbg[(size_t)HEADS * N_TOK * CB_STRIDE + 16];  // rpb gather, 1.4MB

// ---------------- helpers --------------------------------------------------
__device__ __forceinline__ unsigned ex2_f16x2(unsigned x) {
    unsigned r;
    asm("ex2.approx.f16x2 %0, %1;" : "=r"(r) : "r"(x));
    return r;
}

__device__ __forceinline__ unsigned hadd2u(unsigned a, unsigned b) {
    unsigned r;
    asm("add.f16x2 %0, %1, %2;" : "=r"(r) : "r"(a), "r"(b));
    return r;
}

__device__ __forceinline__ unsigned f2tf(float x) {
    unsigned r;
    asm("cvt.rna.tf32.f32 %0, %1;" : "=r"(r) : "f"(x));
    return r;
}

// pack two f32 into f16x2: lo -> lower half, hi -> upper half
__device__ __forceinline__ unsigned pack_f16(float lo, float hi) {
    unsigned d;
    asm("cvt.rn.f16x2.f32 %0, %1, %2;" : "=r"(d) : "f"(hi), "f"(lo));
    return d;
}

__device__ __forceinline__ void mma_tf32(float& c0, float& c1, float& c2, float& c3,
                                         unsigned a0, unsigned a1, unsigned a2, unsigned a3,
                                         unsigned b0, unsigned b1) {
    asm volatile("mma.sync.aligned.m16n8k8.row.col.f32.tf32.tf32.f32 "
                 "{%0,%1,%2,%3}, {%4,%5,%6,%7}, {%8,%9}, {%0,%1,%2,%3};"
                 : "+f"(c0), "+f"(c1), "+f"(c2), "+f"(c3)
                 : "r"(a0), "r"(a1), "r"(a2), "r"(a3), "r"(b0), "r"(b1));
}

__device__ __forceinline__ void mma_f16(float& c0, float& c1, float& c2, float& c3,
                                        unsigned a0, unsigned a1, unsigned a2, unsigned a3,
                                        unsigned b0, unsigned b1) {
    asm volatile("mma.sync.aligned.m16n8k16.row.col.f32.f16.f16.f32 "
                 "{%0,%1,%2,%3}, {%4,%5,%6,%7}, {%8,%9}, {%0,%1,%2,%3};"
                 : "+f"(c0), "+f"(c1), "+f"(c2), "+f"(c3)
                 : "r"(a0), "r"(a1), "r"(a2), "r"(a3), "r"(b0), "r"(b1));
}

// vfrag HALF index for V value at (row j, col d)  (fp16 m16n8k16 B layout)
__device__ __forceinline__ int vhpos(int j, int d) {
    return (((j >> 4) * 4 + (d >> 3)) << 7)
         + (((d & 7) * 4 + ((j >> 1) & 3)) << 2) + (((j >> 3) & 1) << 1) + (j & 1);
}

// ---------------- kernel 0a: rpb gather (once per (h,i,j); 1.4MB out) ------
__global__ __launch_bounds__(352)
void rpbg_kernel(const float* __restrict__ rpb,
                 const int*   __restrict__ relidx) {
    const int i = blockIdx.x;
    const int h = blockIdx.y;
    const int j = threadIdx.x;
    if (j < N_TOK) {
        int rel = relidx[i * N_TOK + j];
        g_rpbg[((size_t)h * N_TOK + i) * CB_STRIDE + j] =
            rpb[rel * HEADS + h] * 1.4426950408889634f;
    }
}

// ---------------- kernel 0b: streaming cb merge (no gather, no smem) -------
__global__ __launch_bounds__(352)
void cb_kernel(const float* __restrict__ mask) {
    const int wh    = blockIdx.x;
    const int chunk = blockIdx.y;
    const int w     = wh / HEADS;
    const int h     = wh - w * HEADS;
    const int tid   = threadIdx.x;

    unsigned* dst = (unsigned*)(g_cb + (size_t)wh * CB_SLICE);
    const float* rg = g_rpbg + (size_t)h * N_TOK * CB_STRIDE;
    const int i0 = chunk * 86;
    const int i1 = (i0 + 86 < N_TOK) ? i0 + 86 : N_TOK;
    for (int i = i0; i < i1; i++) {
        unsigned hb = 0xFC00u;    // fp16 -inf (pad j=343)
        if (tid < N_TOK) {
            float v = fmaf(mask[(size_t)w * N_TOK * N_TOK + i * N_TOK + tid],
                           1.4426950408889634f, rg[i * CB_STRIDE + tid]);
            hb = (unsigned)__half_as_ushort(__float2half_rn(v));
        }
        unsigned up = __shfl_down_sync(0xffffffffu, hb, 1);
        if (!(tid & 1) && tid < CB_STRIDE)
            dst[i * (CB_STRIDE / 2) + (tid >> 1)] = (hb & 0xFFFFu) | (up << 16);
    }
}

// ---------------- kernel 1: FUSED qkv + attention (fp16 prologue) ----------
// One CTA = (window, head). x staged as packed f16x2; W as fp16 m16n8k16
// B-frags; K/V/Q computed with 6 fp16 mma per n8-tile (was 12 tf32).
// Mainloop unchanged from R14/R15 (fully unrolled, ex2.f16x2, ones-mma).
__global__ __launch_bounds__(704, 1)
void attn_kernel(const float* __restrict__ xg,
                 const float* __restrict__ qkvw,
                 const float* __restrict__ qkvb) {
    extern __shared__ unsigned smu[];
    unsigned* kfrag = smu;               // [44*2][64] f16x2       :  5632 words
    unsigned* vfrag = smu + 5632;        // [22*4][64] f16x2       :  5632 words
    unsigned* wf    = smu + 11264;       // [3][4][6][64] f16x2    :  4608 words
    unsigned* xs    = smu + 15872;       // [128][50] f16x2        :  6400 words
    float*    bsm   = (float*)(smu + 22272);   // [96]
    __half*   vh    = (__half*)vfrag;

    const int bid  = blockIdx.x;
    const int wh   = bid >> 3;                 // window*3 + h
    const int rep  = bid & 7;
    const int win  = wh / HEADS;
    const int h    = wh - win * HEADS;
    const int b    = rep * NW + win;
    const int tid  = threadIdx.x;
    const int lane = tid & 31;
    const int w    = tid >> 5;           // 0..21
    const int g    = lane >> 2;          // 0..7
    const int tig  = lane & 3;           // 0..3

    const float* xrow0 = xg + (size_t)b * N_TOK * DIM;
    const __half* cbp  = g_cb + (size_t)wh * CB_SLICE;
    const float qscale = 0.17677669529663687f * 1.4426950408889634f;  // /sqrt(32) * log2e

    // ---- stage fp16 weight B-fragments for this head ----
    // tile t = third*24 + nt*6 + kkc; within tile lane l: c-row = +(l>>2),
    // k-in-chunk = (l&3)*2 (+8 for reg 1), halves = k, k+1
    for (int idx = tid; idx < 3 * 4 * 6 * 32; idx += 704) {
        int t = idx >> 5, l = idx & 31;
        int third = t / 24, rem = t - third * 24;
        int nt = rem / 6, kkc = rem - nt * 6;
        int c  = third * 96 + h * 32 + nt * 8 + (l >> 2);
        int k0 = kkc * 16 + (l & 3) * 2;
        wf[t * 64 + l * 2]     = pack_f16(qkvw[c * 96 + k0],     qkvw[c * 96 + k0 + 1]);
        wf[t * 64 + l * 2 + 1] = pack_f16(qkvw[c * 96 + k0 + 8], qkvw[c * 96 + k0 + 9]);
    }
    for (int idx = tid; idx < 96; idx += 704) {
        bsm[idx] = qkvb[idx + h * 32 + ((idx >> 5) * 64)];  // bsm[third*32+cc] = qkvb[third*96+h*32+cc]
    }

    unsigned qa[2][4];   // fp16 Q A-fragments, 2 k16 chunks

    // ---- chunks of 128 rows: compute K,V into frags; Q for owning warps ----
    #pragma unroll 1
    for (int c = 0; c < 3; c++) {
        if (c > 0) __syncthreads();
        for (int idx = tid; idx < 128 * 48; idx += 704) {
            int r = idx / 48, cw = idx - r * 48;
            int n = 128 * c + r;
            float2 v = (n < N_TOK) ? *(const float2*)(xrow0 + (size_t)n * 96 + cw * 2)
                                   : make_float2(0.f, 0.f);
            xs[r * 50 + cw] = pack_f16(v.x, v.y);
        }
        __syncthreads();

        // K/V units: u = (s<<2) | (third01<<1) | nhalf, 32 units over 22 warps
        for (int u = w; u < 32; u += 22) {
            int s = u >> 2, th = (u >> 1) & 1, nh = u & 1;
            const unsigned* xrA = xs + (s * 16 + g) * 50;
            const unsigned* xrB = xrA + 400;
            #pragma unroll
            for (int ntl = 0; ntl < 2; ntl++) {
                int nt = nh * 2 + ntl;
                float a0f = 0.f, a1f = 0.f, a2f = 0.f, a3f = 0.f;
                #pragma unroll
                for (int kkc = 0; kkc < 6; kkc++) {
                    unsigned a0 = xrA[kkc * 8 + tig];
                    unsigned a1 = xrB[kkc * 8 + tig];
                    unsigned a2 = xrA[kkc * 8 + tig + 4];
                    unsigned a3 = xrB[kkc * 8 + tig + 4];
                    uint2 bb = *(const uint2*)(wf + (((th + 1) * 24) + nt * 6 + kkc) * 64 + lane * 2);
                    mma_f16(a0f, a1f, a2f, a3f, a0, a1, a2, a3, bb.x, bb.y);
                }
                int c0 = nt * 8 + 2 * tig;
                float b0 = bsm[(th + 1) * 32 + c0];
                float b1 = bsm[(th + 1) * 32 + c0 + 1];
                int nA = 128 * c + s * 16 + g;
                int nB = nA + 8;
                float v00 = a0f + b0, v01 = a1f + b1;    // row nA
                float v10 = a2f + b0, v11 = a3f + b1;    // row nB
                if (th == 0) {
                    int tcol = nt >> 1, reg = nt & 1;
                    if (nA < 352)
                        kfrag[((((nA >> 3) << 1) + tcol) << 6) + (lane << 1) + reg] = pack_f16(v00, v01);
                    if (nB < 352)
                        kfrag[((((nB >> 3) << 1) + tcol) << 6) + (lane << 1) + reg] = pack_f16(v10, v11);
                } else {
                    if (nA < 352) {
                        vh[vhpos(nA, c0)]     = __float2half_rn(v00);
                        vh[vhpos(nA, c0 + 1)] = __float2half_rn(v01);
                    }
                    if (nB < 352) {
                        vh[vhpos(nB, c0)]     = __float2half_rn(v10);
                        vh[vhpos(nB, c0 + 1)] = __float2half_rn(v11);
                    }
                }
            }
        }

        // Q for warps whose stripe lives in this chunk: direct fp16 pack
        if ((w >> 3) == c) {
            const int s = w & 7;
            const unsigned* xrA = xs + (s * 16 + g) * 50;
            const unsigned* xrB = xrA + 400;
            #pragma unroll
            for (int nt = 0; nt < 4; nt++) {
                float a0f = 0.f, a1f = 0.f, a2f = 0.f, a3f = 0.f;
                #pragma unroll
                for (int kkc = 0; kkc < 6; kkc++) {
                    unsigned a0 = xrA[kkc * 8 + tig];
                    unsigned a1 = xrB[kkc * 8 + tig];
                    unsigned a2 = xrA[kkc * 8 + tig + 4];
                    unsigned a3 = xrB[kkc * 8 + tig + 4];
                    uint2 bb = *(const uint2*)(wf + (nt * 6 + kkc) * 64 + lane * 2);
                    mma_f16(a0f, a1f, a2f, a3f, a0, a1, a2, a3, bb.x, bb.y);
                }
                int c0 = nt * 8 + 2 * tig;
                float b0 = bsm[c0], b1 = bsm[c0 + 1];
                qa[nt >> 1][(nt & 1) * 2 + 0] = pack_f16((a0f + b0) * qscale, (a1f + b1) * qscale);
                qa[nt >> 1][(nt & 1) * 2 + 1] = pack_f16((a2f + b0) * qscale, (a3f + b1) * qscale);
            }
        }
    }
    __syncthreads();

    // ---- mainloop (fully unrolled; ptxas hoists cb LDGs for deep MLP) ----
    const int i0 = w * 16;
    const int iA = i0 + g, iB = i0 + g + 8;
    const bool vA = (iA < N_TOK), vB = (iB < N_TOK);

    float av[5][4];   // [0..3]: output n8 tiles; [4]: ones-column rowsums
    #pragma unroll
    for (int nn = 0; nn < 5; nn++)
        #pragma unroll
        for (int e = 0; e < 4; e++) av[nn][e] = 0.f;

    const __half* cbAh = cbp + (size_t)iA * CB_STRIDE;
    const __half* cbBh = cbp + (size_t)iB * CB_STRIDE;

    #pragma unroll
    for (int tp = 0; tp < 22; tp++) {
        unsigned af[4];
        #pragma unroll
        for (int tt = 0; tt < 2; tt++) {
            const int ntg = 2 * tp + tt;
            const int j0  = ntg * 8 + 2 * tig;

            unsigned pa, pb;
            if (ntg < 43) {            // compile-time branch
                pa = vA ? *(const unsigned*)(cbAh + j0) : NEGINF2;
                pb = vB ? *(const unsigned*)(cbBh + j0) : NEGINF2;
            } else {
                pa = NEGINF2; pb = NEGINF2;
            }

            float c0 = 0.f, c1 = 0.f, c2 = 0.f, c3 = 0.f;
            uint2 bk0 = *(const uint2*)(kfrag + (ntg * 2 + 0) * 64 + lane * 2);
            uint2 bk1 = *(const uint2*)(kfrag + (ntg * 2 + 1) * 64 + lane * 2);
            mma_f16(c0, c1, c2, c3, qa[0][0], qa[0][1], qa[0][2], qa[0][3], bk0.x, bk0.y);
            mma_f16(c0, c1, c2, c3, qa[1][0], qa[1][1], qa[1][2], qa[1][3], bk1.x, bk1.y);

            unsigned s0 = hadd2u(pack_f16(c0, c1), pa);
            unsigned s1 = hadd2u(pack_f16(c2, c3), pb);
            af[tt * 2 + 0] = ex2_f16x2(s0);   // row g
            af[tt * 2 + 1] = ex2_f16x2(s1);   // row g+8
        }

        #pragma unroll
        for (int nn = 0; nn < 4; nn++) {
            uint2 bb = *(const uint2*)(vfrag + (tp * 4 + nn) * 64 + lane * 2);
            mma_f16(av[nn][0], av[nn][1], av[nn][2], av[nn][3],
                    af[0], af[1], af[2], af[3], bb.x, bb.y);
        }
        mma_f16(av[4][0], av[4][1], av[4][2], av[4][3],
                af[0], af[1], af[2], af[3], ONES_F16X2, ONES_F16X2);
    }

    const float invA = 1.0f / av[4][0];
    const float invB = 1.0f / av[4][2];

    __half* aoh = g_ao;
    #pragma unroll
    for (int nn = 0; nn < 4; nn++) {
        const int d = nn * 8 + 2 * tig;
        if (vA) {
            unsigned o = pack_f16(av[nn][0] * invA, av[nn][1] * invA);
            *(unsigned*)(aoh + ((size_t)b * N_TOK + iA) * DIM + h * HD + d) = o;
        }
        if (vB) {
            unsigned o = pack_f16(av[nn][2] * invB, av[nn][3] * invB);
            *(unsigned*)(aoh + ((size_t)b * N_TOK + iB) * DIM + h * HD + d) = o;
        }
    }
}

// ---------------- kernel 2: output projection (reads fp16 g_ao) ------------
__global__ __launch_bounds__(256, 2)
void proj_kernel(const float* __restrict__ w,
                 const float* __restrict__ bias,
                 float* __restrict__ out) {
    extern __shared__ float smf[];
    unsigned* xs    = (unsigned*)smf;            // [128][100] tf32 bits
    unsigned* wfrag = (unsigned*)smf + 12800;    // [144][64]
    float*    bs    = smf + 12800 + 9216;        // [96]
    const int tid = threadIdx.x;
    const int m0  = blockIdx.x * 128;

    for (int idx = tid; idx < 12 * 12 * 32; idx += 256) {
        int t = idx >> 5, l = idx & 31;
        int nt = t / 12, kk = t - nt * 12;
        int gl = l >> 2, tl = l & 3;
        int c  = nt * 8 + gl;
        int k0 = kk * 8 + tl;
        wfrag[t * 64 + l * 2]     = f2tf(w[c * 96 + k0]);
        wfrag[t * 64 + l * 2 + 1] = f2tf(w[c * 96 + k0 + 4]);
    }
    if (tid < 96) bs[tid] = bias[tid];
    {
        const __half2* src = (const __half2*)(g_ao + (size_t)m0 * 96);
        for (int idx = tid; idx < 128 * 48; idx += 256) {
            int r = idx / 48, c2 = idx - r * 48;
            float2 v = __half22float2(src[idx]);
            xs[r * 100 + c2 * 2]     = f2tf(v.x);
            xs[r * 100 + c2 * 2 + 1] = f2tf(v.y);
        }
    }
    __syncthreads();

    const int wp   = tid >> 5;
    const int lane = tid & 31;
    const int g    = lane >> 2;
    const int tig  = lane & 3;
    const int cg   = wp & 3;
    const int mh   = wp >> 2;

    uint2 breg[12][3];
    #pragma unroll
    for (int kk = 0; kk < 12; kk++)
        #pragma unroll
        for (int ntl = 0; ntl < 3; ntl++)
            breg[kk][ntl] = *(const uint2*)(wfrag + ((3 * cg + ntl) * 12 + kk) * 64 + lane * 2);

    #pragma unroll
    for (int s = 0; s < 4; s++) {
        const unsigned* xrA = xs + (mh * 64 + s * 16 + g) * 100;
        const unsigned* xrB = xrA + 800;

        float acc[3][4];
        #pragma unroll
        for (int ntl = 0; ntl < 3; ntl++)
            #pragma unroll
            for (int e = 0; e < 4; e++) acc[ntl][e] = 0.f;

        #pragma unroll
        for (int kk = 0; kk < 12; kk++) {
            unsigned a0 = xrA[kk * 8 + tig];
            unsigned a1 = xrB[kk * 8 + tig];
            unsigned a2 = xrA[kk * 8 + tig + 4];
            unsigned a3 = xrB[kk * 8 + tig + 4];
            #pragma unroll
            for (int ntl = 0; ntl < 3; ntl++)
                mma_tf32(acc[ntl][0], acc[ntl][1], acc[ntl][2], acc[ntl][3],
                         a0, a1, a2, a3, breg[kk][ntl].x, breg[kk][ntl].y);
        }

        const size_t mA = m0 + mh * 64 + s * 16 + g;
        const size_t mB = mA + 8;
        #pragma unroll
        for (int ntl = 0; ntl < 3; ntl++) {
            int c0 = (3 * cg + ntl) * 8 + 2 * tig;
            float bb0 = bs[c0], bb1 = bs[c0 + 1];
            *(float2*)(out + mA * 96 + c0) = make_float2(acc[ntl][0] + bb0, acc[ntl][1] + bb1);
            *(float2*)(out + mB * 96 + c0) = make_float2(acc[ntl][2] + bb0, acc[ntl][3] + bb1);
        }
    }
}

// ---------------- launch ---------------------------------------------------
extern "C" void kernel_launch(void* const* d_in, const int* in_sizes, int n_in,
                              void* d_out, int out_size) {
    const float* x      = (const float*)d_in[0];
    const float* mask   = (const float*)d_in[1];
    const float* qkv_w  = (const float*)d_in[2];
    const float* qkv_b  = (const float*)d_in[3];
    const float* proj_w = (const float*)d_in[4];
    const float* proj_b = (const float*)d_in[5];
    const float* rpb    = (const float*)d_in[6];
    const int*   relidx = (const int*)d_in[7];
    float* out = (float*)d_out;

    const int smem_attn = (5632 + 5632 + 4608 + 6400 + 96) * 4;  // 89,472 B
    const int smem_proj = (12800 + 9216 + 96) * 4;               // 88,448 B
    cudaFuncSetAttribute(attn_kernel, cudaFuncAttributeMaxDynamicSharedMemorySize, smem_attn);
    cudaFuncSetAttribute(proj_kernel, cudaFuncAttributeMaxDynamicSharedMemorySize, smem_proj);

    rpbg_kernel<<<dim3(N_TOK, HEADS), 352>>>(rpb, relidx);
    cb_kernel  <<<dim3(NW * HEADS, 4), 352>>>(mask);
    attn_kernel<<<B_TOT * HEADS, 704, smem_attn>>>(x, qkv_w, qkv_b);
    proj_kernel<<<1372, 256, smem_proj>>>(proj_w, proj_b, out);
    (void)in_sizes; (void)n_in; (void)out_size;
}

// round 17
// speedup vs baseline: 1.4407x; 1.2061x over previous
#include <cuda_runtime.h>
#include <cuda_fp16.h>
#include <math.h>

#define B_TOT 512
#define N_TOK 343
#define DIM   96
#define HEADS 3
#define HD    32
#define NW    64
#define CB_STRIDE 344
#define CB_SLICE  (N_TOK * CB_STRIDE)   // 117992
#define ONES_F16X2 0x3C003C00u
#define NEGINF2    0xFC00FC00u

// ---------------- scratch (device globals: no allocation allowed) ----------
__device__ __half g_ao[(size_t)B_TOT * N_TOK * DIM];         // [B][N][H*hd] fp16
__device__ __half g_cb[(size_t)NW * HEADS * CB_SLICE + 64];  // (mask+bias)*log2e, fp16
__device__ float  g_rpbg[(size_t)HEADS * N_TOK * CB_STRIDE + 16];  // rpb gather, 1.4MB

// ---------------- helpers --------------------------------------------------
__device__ __forceinline__ unsigned ex2_f16x2(unsigned x) {
    unsigned r;
    asm("ex2.approx.f16x2 %0, %1;" : "=r"(r) : "r"(x));
    return r;
}

__device__ __forceinline__ unsigned hadd2u(unsigned a, unsigned b) {
    unsigned r;
    asm("add.f16x2 %0, %1, %2;" : "=r"(r) : "r"(a), "r"(b));
    return r;
}

// pack two f32 into f16x2: lo -> lower half, hi -> upper half
__device__ __forceinline__ unsigned pack_f16(float lo, float hi) {
    unsigned d;
    asm("cvt.rn.f16x2.f32 %0, %1, %2;" : "=r"(d) : "f"(hi), "f"(lo));
    return d;
}

__device__ __forceinline__ void mma_f16(float& c0, float& c1, float& c2, float& c3,
                                        unsigned a0, unsigned a1, unsigned a2, unsigned a3,
                                        unsigned b0, unsigned b1) {
    asm volatile("mma.sync.aligned.m16n8k16.row.col.f32.f16.f16.f32 "
                 "{%0,%1,%2,%3}, {%4,%5,%6,%7}, {%8,%9}, {%0,%1,%2,%3};"
                 : "+f"(c0), "+f"(c1), "+f"(c2), "+f"(c3)
                 : "r"(a0), "r"(a1), "r"(a2), "r"(a3), "r"(b0), "r"(b1));
}

// vfrag HALF index for V value at (row j, col d)  (fp16 m16n8k16 B layout)
__device__ __forceinline__ int vhpos(int j, int d) {
    return (((j >> 4) * 4 + (d >> 3)) << 7)
         + (((d & 7) * 4 + ((j >> 1) & 3)) << 2) + (((j >> 3) & 1) << 1) + (j & 1);
}

// ---------------- kernel 0a: rpb gather (once per (h,i,j); 1.4MB out) ------
__global__ __launch_bounds__(352)
void rpbg_kernel(const float* __restrict__ rpb,
                 const int*   __restrict__ relidx) {
    const int i = blockIdx.x;
    const int h = blockIdx.y;
    const int j = threadIdx.x;
    if (j < N_TOK) {
        int rel = relidx[i * N_TOK + j];
        g_rpbg[((size_t)h * N_TOK + i) * CB_STRIDE + j] =
            rpb[rel * HEADS + h] * 1.4426950408889634f;
    }
}

// ---------------- kernel 0b: streaming cb merge (no gather, no smem) -------
__global__ __launch_bounds__(352)
void cb_kernel(const float* __restrict__ mask) {
    const int wh    = blockIdx.x;
    const int chunk = blockIdx.y;
    const int w     = wh / HEADS;
    const int h     = wh - w * HEADS;
    const int tid   = threadIdx.x;

    unsigned* dst = (unsigned*)(g_cb + (size_t)wh * CB_SLICE);
    const float* rg = g_rpbg + (size_t)h * N_TOK * CB_STRIDE;
    const int i0 = chunk * 86;
    const int i1 = (i0 + 86 < N_TOK) ? i0 + 86 : N_TOK;
    for (int i = i0; i < i1; i++) {
        unsigned hb = 0xFC00u;    // fp16 -inf (pad j=343)
        if (tid < N_TOK) {
            float v = fmaf(mask[(size_t)w * N_TOK * N_TOK + i * N_TOK + tid],
                           1.4426950408889634f, rg[i * CB_STRIDE + tid]);
            hb = (unsigned)__half_as_ushort(__float2half_rn(v));
        }
        unsigned up = __shfl_down_sync(0xffffffffu, hb, 1);
        if (!(tid & 1) && tid < CB_STRIDE)
            dst[i * (CB_STRIDE / 2) + (tid >> 1)] = (hb & 0xFFFFu) | (up << 16);
    }
}

// ---------------- kernel 1: FUSED qkv + attention --------------------------
// One CTA = (window, head). Single-shot prologue: stage ALL 352 x-rows once,
// one barrier, then K/V as 88 balanced units (4/warp) + per-warp Q stripe,
// one barrier, mainloop. Everything fp16 mma with f32 accumulation.
__global__ __launch_bounds__(704, 1)
void attn_kernel(const float* __restrict__ xg,
                 const float* __restrict__ qkvw,
                 const float* __restrict__ qkvb) {
    extern __shared__ unsigned smu[];
    unsigned* kfrag = smu;               // [44*2][64] f16x2       :  5632 words
    unsigned* vfrag = smu + 5632;        // [22*4][64] f16x2       :  5632 words
    unsigned* wf    = smu + 11264;       // [3][4][6][64] f16x2    :  4608 words
    unsigned* xs    = smu + 15872;       // [352][52] f16x2        : 18304 words
    float*    bsm   = (float*)(smu + 34176);   // [96]
    __half*   vh    = (__half*)vfrag;

    const int bid  = blockIdx.x;
    const int wh   = bid >> 3;                 // window*3 + h
    const int rep  = bid & 7;
    const int win  = wh / HEADS;
    const int h    = wh - win * HEADS;
    const int b    = rep * NW + win;
    const int tid  = threadIdx.x;
    const int lane = tid & 31;
    const int w    = tid >> 5;           // 0..21
    const int g    = lane >> 2;          // 0..7
    const int tig  = lane & 3;           // 0..3

    const float* xrow0 = xg + (size_t)b * N_TOK * DIM;
    const __half* cbp  = g_cb + (size_t)wh * CB_SLICE;
    const float qscale = 0.17677669529663687f * 1.4426950408889634f;  // /sqrt(32) * log2e

    // ---- stage fp16 weight B-fragments for this head ----
    for (int idx = tid; idx < 3 * 4 * 6 * 32; idx += 704) {
        int t = idx >> 5, l = idx & 31;
        int third = t / 24, rem = t - third * 24;
        int nt = rem / 6, kkc = rem - nt * 6;
        int c  = third * 96 + h * 32 + nt * 8 + (l >> 2);
        int k0 = kkc * 16 + (l & 3) * 2;
        wf[t * 64 + l * 2]     = pack_f16(qkvw[c * 96 + k0],     qkvw[c * 96 + k0 + 1]);
        wf[t * 64 + l * 2 + 1] = pack_f16(qkvw[c * 96 + k0 + 8], qkvw[c * 96 + k0 + 9]);
    }
    for (int idx = tid; idx < 96; idx += 704) {
        bsm[idx] = qkvb[idx + h * 32 + ((idx >> 5) * 64)];  // bsm[third*32+cc] = qkvb[third*96+h*32+cc]
    }

    // ---- stage ALL x rows as packed f16x2 (rows >= N_TOK zeroed) ----
    for (int idx = tid; idx < 352 * 48; idx += 704) {
        int r = idx / 48, cw = idx - r * 48;
        float2 v = (r < N_TOK) ? *(const float2*)(xrow0 + (size_t)r * 96 + cw * 2)
                               : make_float2(0.f, 0.f);
        xs[r * 52 + cw] = pack_f16(v.x, v.y);
    }
    __syncthreads();

    // ---- K/V: 88 units (s:22 x th:2 x nh:2), exactly 4 per warp ----
    for (int u = w; u < 88; u += 22) {
        int s = u >> 2, th = (u >> 1) & 1, nh = u & 1;
        const unsigned* xrA = xs + (s * 16 + g) * 52;
        const unsigned* xrB = xrA + 416;
        #pragma unroll
        for (int ntl = 0; ntl < 2; ntl++) {
            int nt = nh * 2 + ntl;
            float a0f = 0.f, a1f = 0.f, a2f = 0.f, a3f = 0.f;
            #pragma unroll
            for (int kkc = 0; kkc < 6; kkc++) {
                unsigned a0 = xrA[kkc * 8 + tig];
                unsigned a1 = xrB[kkc * 8 + tig];
                unsigned a2 = xrA[kkc * 8 + tig + 4];
                unsigned a3 = xrB[kkc * 8 + tig + 4];
                uint2 bb = *(const uint2*)(wf + (((th + 1) * 24) + nt * 6 + kkc) * 64 + lane * 2);
                mma_f16(a0f, a1f, a2f, a3f, a0, a1, a2, a3, bb.x, bb.y);
            }
            int c0 = nt * 8 + 2 * tig;
            float b0 = bsm[(th + 1) * 32 + c0];
            float b1 = bsm[(th + 1) * 32 + c0 + 1];
            int nA = s * 16 + g;
            int nB = nA + 8;
            float v00 = a0f + b0, v01 = a1f + b1;    // row nA
            float v10 = a2f + b0, v11 = a3f + b1;    // row nB
            if (th == 0) {
                int tcol = nt >> 1, reg = nt & 1;
                kfrag[((((nA >> 3) << 1) + tcol) << 6) + (lane << 1) + reg] = pack_f16(v00, v01);
                kfrag[((((nB >> 3) << 1) + tcol) << 6) + (lane << 1) + reg] = pack_f16(v10, v11);
            } else {
                vh[vhpos(nA, c0)]     = __float2half_rn(v00);
                vh[vhpos(nA, c0 + 1)] = __float2half_rn(v01);
                vh[vhpos(nB, c0)]     = __float2half_rn(v10);
                vh[vhpos(nB, c0 + 1)] = __float2half_rn(v11);
            }
        }
    }

    // ---- Q: each warp computes its own stripe ----
    unsigned qa[2][4];
    {
        const unsigned* xrA = xs + (w * 16 + g) * 52;
        const unsigned* xrB = xrA + 416;
        #pragma unroll
        for (int nt = 0; nt < 4; nt++) {
            float a0f = 0.f, a1f = 0.f, a2f = 0.f, a3f = 0.f;
            #pragma unroll
            for (int kkc = 0; kkc < 6; kkc++) {
                unsigned a0 = xrA[kkc * 8 + tig];
                unsigned a1 = xrB[kkc * 8 + tig];
                unsigned a2 = xrA[kkc * 8 + tig + 4];
                unsigned a3 = xrB[kkc * 8 + tig + 4];
                uint2 bb = *(const uint2*)(wf + (nt * 6 + kkc) * 64 + lane * 2);
                mma_f16(a0f, a1f, a2f, a3f, a0, a1, a2, a3, bb.x, bb.y);
            }
            int c0 = nt * 8 + 2 * tig;
            float b0 = bsm[c0], b1 = bsm[c0 + 1];
            qa[nt >> 1][(nt & 1) * 2 + 0] = pack_f16((a0f + b0) * qscale, (a1f + b1) * qscale);
            qa[nt >> 1][(nt & 1) * 2 + 1] = pack_f16((a2f + b0) * qscale, (a3f + b1) * qscale);
        }
    }
    __syncthreads();

    // ---- mainloop (fully unrolled; ptxas hoists cb LDGs for deep MLP) ----
    const int i0 = w * 16;
    const int iA = i0 + g, iB = i0 + g + 8;
    const bool vA = (iA < N_TOK), vB = (iB < N_TOK);

    float av[5][4];   // [0..3]: output n8 tiles; [4]: ones-column rowsums
    #pragma unroll
    for (int nn = 0; nn < 5; nn++)
        #pragma unroll
        for (int e = 0; e < 4; e++) av[nn][e] = 0.f;

    const __half* cbAh = cbp + (size_t)iA * CB_STRIDE;
    const __half* cbBh = cbp + (size_t)iB * CB_STRIDE;

    #pragma unroll
    for (int tp = 0; tp < 22; tp++) {
        unsigned af[4];
        #pragma unroll
        for (int tt = 0; tt < 2; tt++) {
            const int ntg = 2 * tp + tt;
            const int j0  = ntg * 8 + 2 * tig;

            unsigned pa, pb;
            if (ntg < 43) {            // compile-time branch
                pa = vA ? *(const unsigned*)(cbAh + j0) : NEGINF2;
                pb = vB ? *(const unsigned*)(cbBh + j0) : NEGINF2;
            } else {
                pa = NEGINF2; pb = NEGINF2;
            }

            float c0 = 0.f, c1 = 0.f, c2 = 0.f, c3 = 0.f;
            uint2 bk0 = *(const uint2*)(kfrag + (ntg * 2 + 0) * 64 + lane * 2);
            uint2 bk1 = *(const uint2*)(kfrag + (ntg * 2 + 1) * 64 + lane * 2);
            mma_f16(c0, c1, c2, c3, qa[0][0], qa[0][1], qa[0][2], qa[0][3], bk0.x, bk0.y);
            mma_f16(c0, c1, c2, c3, qa[1][0], qa[1][1], qa[1][2], qa[1][3], bk1.x, bk1.y);

            unsigned s0 = hadd2u(pack_f16(c0, c1), pa);
            unsigned s1 = hadd2u(pack_f16(c2, c3), pb);
            af[tt * 2 + 0] = ex2_f16x2(s0);   // row g
            af[tt * 2 + 1] = ex2_f16x2(s1);   // row g+8
        }

        #pragma unroll
        for (int nn = 0; nn < 4; nn++) {
            uint2 bb = *(const uint2*)(vfrag + (tp * 4 + nn) * 64 + lane * 2);
            mma_f16(av[nn][0], av[nn][1], av[nn][2], av[nn][3],
                    af[0], af[1], af[2], af[3], bb.x, bb.y);
        }
        mma_f16(av[4][0], av[4][1], av[4][2], av[4][3],
                af[0], af[1], af[2], af[3], ONES_F16X2, ONES_F16X2);
    }

    const float invA = 1.0f / av[4][0];
    const float invB = 1.0f / av[4][2];

    __half* aoh = g_ao;
    #pragma unroll
    for (int nn = 0; nn < 4; nn++) {
        const int d = nn * 8 + 2 * tig;
        if (vA) {
            unsigned o = pack_f16(av[nn][0] * invA, av[nn][1] * invA);
            *(unsigned*)(aoh + ((size_t)b * N_TOK + iA) * DIM + h * HD + d) = o;
        }
        if (vB) {
            unsigned o = pack_f16(av[nn][2] * invB, av[nn][3] * invB);
            *(unsigned*)(aoh + ((size_t)b * N_TOK + iB) * DIM + h * HD + d) = o;
        }
    }
}

// ---------------- kernel 2: output projection, fp16 mma, 3 CTAs/SM ---------
__global__ __launch_bounds__(256, 3)
void proj_kernel(const float* __restrict__ w,
                 const float* __restrict__ bias,
                 float* __restrict__ out) {
    extern __shared__ unsigned smp[];
    unsigned* xs    = smp;               // [128][52] f16x2 : 6656 words
    unsigned* wfrag = smp + 6656;        // [12][6][64]     : 4608 words
    float*    bs    = (float*)(smp + 11264);   // [96]
    const int tid = threadIdx.x;
    const int m0  = blockIdx.x * 128;

    for (int idx = tid; idx < 12 * 6 * 32; idx += 256) {
        int t = idx >> 5, l = idx & 31;
        int nt = t / 6, kkc = t - nt * 6;
        int c  = nt * 8 + (l >> 2);
        int k0 = kkc * 16 + (l & 3) * 2;
        wfrag[t * 64 + l * 2]     = pack_f16(w[c * 96 + k0],     w[c * 96 + k0 + 1]);
        wfrag[t * 64 + l * 2 + 1] = pack_f16(w[c * 96 + k0 + 8], w[c * 96 + k0 + 9]);
    }
    if (tid < 96) bs[tid] = bias[tid];
    {
        const unsigned* src = (const unsigned*)(g_ao + (size_t)m0 * 96);
        for (int idx = tid; idx < 128 * 48; idx += 256) {
            int r = idx / 48, cw = idx - r * 48;
            xs[r * 52 + cw] = src[idx];      // raw fp16 copy, no conversion
        }
    }
    __syncthreads();

    const int wp   = tid >> 5;
    const int lane = tid & 31;
    const int g    = lane >> 2;
    const int tig  = lane & 3;
    const int cg   = wp & 3;
    const int mh   = wp >> 2;

    uint2 breg[6][3];
    #pragma unroll
    for (int kkc = 0; kkc < 6; kkc++)
        #pragma unroll
        for (int ntl = 0; ntl < 3; ntl++)
            breg[kkc][ntl] = *(const uint2*)(wfrag + ((3 * cg + ntl) * 6 + kkc) * 64 + lane * 2);

    #pragma unroll
    for (int s = 0; s < 4; s++) {
        const unsigned* xrA = xs + (mh * 64 + s * 16 + g) * 52;
        const unsigned* xrB = xrA + 416;

        float acc[3][4];
        #pragma unroll
        for (int ntl = 0; ntl < 3; ntl++)
            #pragma unroll
            for (int e = 0; e < 4; e++) acc[ntl][e] = 0.f;

        #pragma unroll
        for (int kkc = 0; kkc < 6; kkc++) {
            unsigned a0 = xrA[kkc * 8 + tig];
            unsigned a1 = xrB[kkc * 8 + tig];
            unsigned a2 = xrA[kkc * 8 + tig + 4];
            unsigned a3 = xrB[kkc * 8 + tig + 4];
            #pragma unroll
            for (int ntl = 0; ntl < 3; ntl++)
                mma_f16(acc[ntl][0], acc[ntl][1], acc[ntl][2], acc[ntl][3],
                        a0, a1, a2, a3, breg[kkc][ntl].x, breg[kkc][ntl].y);
        }

        const size_t mA = m0 + mh * 64 + s * 16 + g;
        const size_t mB = mA + 8;
        #pragma unroll
        for (int ntl = 0; ntl < 3; ntl++) {
            int c0 = (3 * cg + ntl) * 8 + 2 * tig;
            float bb0 = bs[c0], bb1 = bs[c0 + 1];
            *(float2*)(out + mA * 96 + c0) = make_float2(acc[ntl][0] + bb0, acc[ntl][1] + bb1);
            *(float2*)(out + mB * 96 + c0) = make_float2(acc[ntl][2] + bb0, acc[ntl][3] + bb1);
        }
    }
}

// ---------------- launch ---------------------------------------------------
extern "C" void kernel_launch(void* const* d_in, const int* in_sizes, int n_in,
                              void* d_out, int out_size) {
    const float* x      = (const float*)d_in[0];
    const float* mask   = (const float*)d_in[1];
    const float* qkv_w  = (const float*)d_in[2];
    const float* qkv_b  = (const float*)d_in[3];
    const float* proj_w = (const float*)d_in[4];
    const float* proj_b = (const float*)d_in[5];
    const float* rpb    = (const float*)d_in[6];
    const int*   relidx = (const int*)d_in[7];
    float* out = (float*)d_out;

    const int smem_attn = (5632 + 5632 + 4608 + 18304 + 96) * 4;  // 137,088 B
    const int smem_proj = (6656 + 4608 + 96) * 4;                 //  45,440 B
    cudaFuncSetAttribute(attn_kernel, cudaFuncAttributeMaxDynamicSharedMemorySize, smem_attn);
    cudaFuncSetAttribute(proj_kernel, cudaFuncAttributeMaxDynamicSharedMemorySize, smem_proj);

    rpbg_kernel<<<dim3(N_TOK, HEADS), 352>>>(rpb, relidx);
    cb_kernel  <<<dim3(NW * HEADS, 4), 352>>>(mask);
    attn_kernel<<<B_TOT * HEADS, 704, smem_attn>>>(x, qkv_w, qkv_b);
    proj_kernel<<<1372, 256, smem_proj>>>(proj_w, proj_b, out);
    (void)in_sizes; (void)n_in; (void)out_size;
}